// round 10
// baseline (speedup 1.0000x reference)
#include <cuda_runtime.h>
#include <cuda_bf16.h>

#define D 64
#define MAXN 100000
#define MAXE 1600000
#define ALPHA 0.2f
#define EPS 1e-10f

// ---------------- device scratch ----------------
__device__ __align__(16) float g_vq[D];
__device__ __align__(16) float g_vk[D];
__device__ float g_cq;
__device__ float g_ck;
__device__ int   g_is64;
__device__ __align__(16) float g_qs[MAXN];
__device__ __align__(16) float g_ks[MAXN];
__device__ __align__(16) float g_kvproj[MAXN * D];   // 25.6MB, L2-resident
__device__ int   g_cnt[MAXN];        // histogram
__device__ int   g_off[MAXN + 1];    // CSR row offsets
__device__ int   g_pos[MAXN];        // scatter cursors
__device__ int   g_ki[MAXE];         // sorted-by-qi kv indices
__device__ float g_w[MAXE];          // sorted-by-qi exp weights

// ---------------- kernel 0: sniff edge_index dtype ----------------
__global__ void sniff_kernel(const int* __restrict__ ei32) {
    if (threadIdx.x == 0) {
        int zeros = 0;
        for (int i = 1; i < 256; i += 2) zeros += (ei32[i] == 0);
        g_is64 = (zeros >= 120) ? 1 : 0;
    }
}

// ---------------- kernel 1: fold attend_w through proj_w ----------------
__global__ void prep_kernel(const float* __restrict__ W, const float* __restrict__ b,
                            const float* __restrict__ aw, const float* __restrict__ ab) {
    int t = threadIdx.x;
    if (t < D) {
        float s = 0.f;
        for (int d = 0; d < D; d++) s += aw[d] * W[d * D + t];
        g_vq[t] = s;
    } else {
        int k = t - D;
        float s = 0.f;
        for (int d = 0; d < D; d++) s += aw[D + d] * W[d * D + k];
        g_vk[k] = s;
    }
    if (t == 0) {
        float cq = 0.f, ck = 0.f;
        for (int d = 0; d < D; d++) { cq += b[d] * aw[d]; ck += b[d] * aw[D + d]; }
        g_cq = cq;
        g_ck = ck + ab[0];
    }
}

// ---------------- kernel 2: per-node attention scalars ----------------
__global__ void scalars_kernel(const float* __restrict__ q, const float* __restrict__ kv,
                               int Nq, int Nk) {
    int lane = threadIdx.x & 31;
    int warp = (blockIdx.x * blockDim.x + threadIdx.x) >> 5;
    int nwarps = (gridDim.x * blockDim.x) >> 5;
    float vq0 = g_vq[lane], vq1 = g_vq[lane + 32];
    float vk0 = g_vk[lane], vk1 = g_vk[lane + 32];
    float cq = g_cq, ck = g_ck;
    int Nmax = Nq > Nk ? Nq : Nk;
    for (int n = warp; n < Nmax; n += nwarps) {
        if (n < Nq) {
            float a = q[n * D + lane] * vq0 + q[n * D + lane + 32] * vq1;
            #pragma unroll
            for (int off = 16; off; off >>= 1) a += __shfl_xor_sync(0xffffffffu, a, off);
            if (lane == 0) g_qs[n] = a + cq;
        }
        if (n < Nk) {
            float a = kv[n * D + lane] * vk0 + kv[n * D + lane + 32] * vk1;
            #pragma unroll
            for (int off = 16; off; off >>= 1) a += __shfl_xor_sync(0xffffffffu, a, off);
            if (lane == 0) g_ks[n] = a + ck;
        }
    }
}

// ---------------- kernel 3: kv projection — register-blocked tiled GEMM ----------------
#define KV_PAD 76
__global__ void kvproj_kernel(const float* __restrict__ kv, const float* __restrict__ W,
                              const float* __restrict__ b, int Nk) {
    __shared__ __align__(16) float Wp[D * KV_PAD];
    __shared__ __align__(16) float Xs[D * KV_PAD];
    int tid = threadIdx.x;
    int tx = tid & 15, ty = tid >> 4;

    for (int i = tid; i < D * 16; i += 256) {
        int d = i >> 4, kq = i & 15;
        float4 w4 = ((const float4*)W)[i];
        *(float4*)&Wp[d * KV_PAD + kq * 4] = w4;
    }
    float bd[4];
    #pragma unroll
    for (int j = 0; j < 4; j++) bd[j] = b[tx + 16 * j];

    int ntiles = (Nk + 63) >> 6;
    for (int tile = blockIdx.x; tile < ntiles; tile += gridDim.x) {
        int base = tile << 6;
        __syncthreads();
        for (int i = tid; i < D * 16; i += 256) {
            int n = i >> 4, kq = i & 15;
            int gn = base + n;
            float4 v = (gn < Nk) ? ((const float4*)kv)[gn * 16 + kq]
                                 : make_float4(0.f, 0.f, 0.f, 0.f);
            *(float4*)&Xs[n * KV_PAD + kq * 4] = v;
        }
        __syncthreads();

        float acc[4][4];
        #pragma unroll
        for (int i = 0; i < 4; i++)
            #pragma unroll
            for (int j = 0; j < 4; j++) acc[i][j] = 0.f;

        #pragma unroll
        for (int k = 0; k < D; k += 4) {
            float4 xv[4], wv[4];
            #pragma unroll
            for (int i = 0; i < 4; i++) xv[i] = *(const float4*)&Xs[(ty + 16 * i) * KV_PAD + k];
            #pragma unroll
            for (int j = 0; j < 4; j++) wv[j] = *(const float4*)&Wp[(tx + 16 * j) * KV_PAD + k];
            #pragma unroll
            for (int i = 0; i < 4; i++)
                #pragma unroll
                for (int j = 0; j < 4; j++) {
                    acc[i][j] += xv[i].x * wv[j].x;
                    acc[i][j] += xv[i].y * wv[j].y;
                    acc[i][j] += xv[i].z * wv[j].z;
                    acc[i][j] += xv[i].w * wv[j].w;
                }
        }

        #pragma unroll
        for (int i = 0; i < 4; i++) {
            int gn = base + ty + 16 * i;
            if (gn < Nk) {
                #pragma unroll
                for (int j = 0; j < 4; j++)
                    g_kvproj[gn * D + tx + 16 * j] = acc[i][j] + bd[j];
            }
        }
    }
}

// ---------------- kernel 4: zero histogram ----------------
__global__ void zerocnt_kernel(int Nq) {
    int i = blockIdx.x * blockDim.x + threadIdx.x;
    if (i < Nq) g_cnt[i] = 0;
}

// ---------------- kernel 5: histogram of qi ----------------
__global__ void hist_kernel(const int* __restrict__ ei32, int E, int Nq) {
    int e = blockIdx.x * blockDim.x + threadIdx.x;
    if (e >= E) return;
    int qi = g_is64 ? (int)((const long long*)ei32)[e] : ei32[e];
    qi = min(max(qi, 0), Nq - 1);
    atomicAdd(&g_cnt[qi], 1);
}

// ---------------- kernel 6: exclusive prefix sum (1 block, shuffle scan) ----------------
__global__ void scan_kernel(int Nq) {
    __shared__ int warp_tot[32];
    __shared__ int warp_pre[32];
    __shared__ int carry_s;
    int tid = threadIdx.x;           // 1024
    int lane = tid & 31, wid = tid >> 5;
    if (tid == 0) carry_s = 0;
    __syncthreads();
    for (int base = 0; base < Nq; base += 1024) {
        int i = base + tid;
        int v = (i < Nq) ? g_cnt[i] : 0;
        // warp inclusive scan
        int incl = v;
        #pragma unroll
        for (int off = 1; off < 32; off <<= 1) {
            int t = __shfl_up_sync(0xffffffffu, incl, off);
            if (lane >= off) incl += t;
        }
        if (lane == 31) warp_tot[wid] = incl;
        __syncthreads();
        if (wid == 0) {
            int wv = warp_tot[lane];
            int winc = wv;
            #pragma unroll
            for (int off = 1; off < 32; off <<= 1) {
                int t = __shfl_up_sync(0xffffffffu, winc, off);
                if (lane >= off) winc += t;
            }
            warp_pre[lane] = winc - wv;     // exclusive
            if (lane == 31) warp_tot[0] = winc;  // chunk total stashed
        }
        __syncthreads();
        int excl = incl - v + warp_pre[wid] + carry_s;
        if (i < Nq) { g_off[i] = excl; g_pos[i] = excl; }
        __syncthreads();
        if (tid == 0) carry_s += warp_tot[0];
        __syncthreads();
    }
    if (tid == 0) g_off[Nq] = carry_s;      // == E
}

// ---------------- kernel 7: scatter (ki, w) into CSR order ----------------
__global__ void scatter_kernel(const int* __restrict__ ei32, int E, int Nq, int Nk) {
    int e = blockIdx.x * blockDim.x + threadIdx.x;
    if (e >= E) return;
    int qi, ki;
    if (g_is64) {
        const long long* ei = (const long long*)ei32;
        qi = (int)ei[e];
        ki = (int)ei[E + e];
    } else {
        qi = ei32[e];
        ki = ei32[E + e];
    }
    qi = min(max(qi, 0), Nq - 1);
    ki = min(max(ki, 0), Nk - 1);
    float s = g_qs[qi] + g_ks[ki];
    s = s > 0.f ? s : ALPHA * s;
    float w = __expf(s);
    int pos = atomicAdd(&g_pos[qi], 1);
    g_ki[pos] = ki;
    g_w[pos]  = w;
}

// ---------------- kernel 8: aggregate — warp per q-node, no atomics ----------------
__global__ void agg_kernel(float* __restrict__ out, int Nq) {
    int warp = (blockIdx.x * blockDim.x + threadIdx.x) >> 5;
    if (warp >= Nq) return;
    int lane = threadIdx.x & 31;
    int j   = g_off[warp];
    int end = g_off[warp + 1];
    float a0 = 0.f, a1 = 0.f, ws = 0.f;
    // unrolled-by-2 main loop for MLP on the gather chain
    for (; j + 2 <= end; j += 2) {
        int   k0 = g_ki[j],     k1 = g_ki[j + 1];
        float w0 = g_w[j],      w1 = g_w[j + 1];
        float v00 = g_kvproj[k0 * D + lane];
        float v01 = g_kvproj[k0 * D + 32 + lane];
        float v10 = g_kvproj[k1 * D + lane];
        float v11 = g_kvproj[k1 * D + 32 + lane];
        a0 += w0 * v00 + w1 * v10;
        a1 += w0 * v01 + w1 * v11;
        ws += w0 + w1;
    }
    if (j < end) {
        int   k0 = g_ki[j];
        float w0 = g_w[j];
        a0 += w0 * g_kvproj[k0 * D + lane];
        a1 += w0 * g_kvproj[k0 * D + 32 + lane];
        ws += w0;
    }
    float inv = 1.f / (ws + EPS);
    out[warp * D + lane]      = a0 * inv;
    out[warp * D + 32 + lane] = a1 * inv;
}

// ---------------- launch ----------------
extern "C" void kernel_launch(void* const* d_in, const int* in_sizes, int n_in,
                              void* d_out, int out_size) {
    const float* q    = (const float*)d_in[0];
    const float* kv   = (const float*)d_in[1];
    const int*   ei32 = (const int*)d_in[2];
    const float* W    = (const float*)d_in[3];
    const float* b    = (const float*)d_in[4];
    const float* aw   = (const float*)d_in[5];
    const float* ab   = (const float*)d_in[6];
    int Nq = in_sizes[0] / D;
    int Nk = in_sizes[1] / D;
    int E  = in_sizes[2] / 2;
    float* out = (float*)d_out;

    sniff_kernel<<<1, 32>>>(ei32);
    prep_kernel<<<1, 128>>>(W, b, aw, ab);

    int Nmax = Nq > Nk ? Nq : Nk;
    int sc_blocks = (Nmax * 32 + 255) / 256;
    if (sc_blocks > 16384) sc_blocks = 16384;
    scalars_kernel<<<sc_blocks, 256>>>(q, kv, Nq, Nk);

    kvproj_kernel<<<592, 256>>>(kv, W, b, Nk);

    zerocnt_kernel<<<(Nq + 255) / 256, 256>>>(Nq);
    hist_kernel<<<(E + 255) / 256, 256>>>(ei32, E, Nq);
    scan_kernel<<<1, 1024>>>(Nq);
    scatter_kernel<<<(E + 255) / 256, 256>>>(ei32, E, Nq, Nk);

    int agg_blocks = (Nq * 32 + 255) / 256;
    agg_kernel<<<agg_blocks, 256>>>(out, Nq);
}

// round 13
// speedup vs baseline: 1.3813x; 1.3813x over previous
#include <cuda_runtime.h>
#include <cuda_bf16.h>

#define D 64
#define MAXN 100000
#define MAXE 1600000
#define ALPHA 0.2f
#define EPS 1e-10f

// ---------------- device scratch ----------------
__device__ __align__(16) float g_vq[D];
__device__ __align__(16) float g_vk[D];
__device__ float g_cq;
__device__ float g_ck;
__device__ int   g_is64;
__device__ __align__(16) float g_qs[MAXN];
__device__ __align__(16) float g_ks[MAXN];
__device__ __align__(16) float g_kvproj[MAXN * D];   // 25.6MB, L2-resident
__device__ __align__(16) float g_esum[MAXN];

// ---------------- kernel 0: sniff edge_index dtype ----------------
__global__ void sniff_kernel(const int* __restrict__ ei32) {
    if (threadIdx.x == 0) {
        int zeros = 0;
        for (int i = 1; i < 256; i += 2) zeros += (ei32[i] == 0);
        g_is64 = (zeros >= 120) ? 1 : 0;
    }
}

// ---------------- kernel 1: fold attend_w through proj_w ----------------
__global__ void prep_kernel(const float* __restrict__ W, const float* __restrict__ b,
                            const float* __restrict__ aw, const float* __restrict__ ab) {
    int t = threadIdx.x;
    if (t < D) {
        float s = 0.f;
        for (int d = 0; d < D; d++) s += aw[d] * W[d * D + t];
        g_vq[t] = s;
    } else {
        int k = t - D;
        float s = 0.f;
        for (int d = 0; d < D; d++) s += aw[D + d] * W[d * D + k];
        g_vk[k] = s;
    }
    if (t == 0) {
        float cq = 0.f, ck = 0.f;
        for (int d = 0; d < D; d++) { cq += b[d] * aw[d]; ck += b[d] * aw[D + d]; }
        g_cq = cq;
        g_ck = ck + ab[0];
    }
}

// ---------------- kernel 2: per-node attention scalars ----------------
__global__ void scalars_kernel(const float* __restrict__ q, const float* __restrict__ kv,
                               int Nq, int Nk) {
    int lane = threadIdx.x & 31;
    int warp = (blockIdx.x * blockDim.x + threadIdx.x) >> 5;
    int nwarps = (gridDim.x * blockDim.x) >> 5;
    float vq0 = g_vq[lane], vq1 = g_vq[lane + 32];
    float vk0 = g_vk[lane], vk1 = g_vk[lane + 32];
    float cq = g_cq, ck = g_ck;
    int Nmax = Nq > Nk ? Nq : Nk;
    for (int n = warp; n < Nmax; n += nwarps) {
        if (n < Nq) {
            float a = q[n * D + lane] * vq0 + q[n * D + lane + 32] * vq1;
            #pragma unroll
            for (int off = 16; off; off >>= 1) a += __shfl_xor_sync(0xffffffffu, a, off);
            if (lane == 0) g_qs[n] = a + cq;
        }
        if (n < Nk) {
            float a = kv[n * D + lane] * vk0 + kv[n * D + lane + 32] * vk1;
            #pragma unroll
            for (int off = 16; off; off >>= 1) a += __shfl_xor_sync(0xffffffffu, a, off);
            if (lane == 0) g_ks[n] = a + ck;
        }
    }
}

// ---------------- kernel 3: kv projection — register-blocked tiled GEMM ----------------
#define KV_PAD 76
__global__ void kvproj_kernel(const float* __restrict__ kv, const float* __restrict__ W,
                              const float* __restrict__ b, int Nk) {
    __shared__ __align__(16) float Wp[D * KV_PAD];
    __shared__ __align__(16) float Xs[D * KV_PAD];
    int tid = threadIdx.x;
    int tx = tid & 15, ty = tid >> 4;

    for (int i = tid; i < D * 16; i += 256) {
        int d = i >> 4, kq = i & 15;
        float4 w4 = ((const float4*)W)[i];
        *(float4*)&Wp[d * KV_PAD + kq * 4] = w4;
    }
    float bd[4];
    #pragma unroll
    for (int j = 0; j < 4; j++) bd[j] = b[tx + 16 * j];

    int ntiles = (Nk + 63) >> 6;
    for (int tile = blockIdx.x; tile < ntiles; tile += gridDim.x) {
        int base = tile << 6;
        __syncthreads();
        for (int i = tid; i < D * 16; i += 256) {
            int n = i >> 4, kq = i & 15;
            int gn = base + n;
            float4 v = (gn < Nk) ? ((const float4*)kv)[gn * 16 + kq]
                                 : make_float4(0.f, 0.f, 0.f, 0.f);
            *(float4*)&Xs[n * KV_PAD + kq * 4] = v;
        }
        __syncthreads();

        float acc[4][4];
        #pragma unroll
        for (int i = 0; i < 4; i++)
            #pragma unroll
            for (int j = 0; j < 4; j++) acc[i][j] = 0.f;

        #pragma unroll
        for (int k = 0; k < D; k += 4) {
            float4 xv[4], wv[4];
            #pragma unroll
            for (int i = 0; i < 4; i++) xv[i] = *(const float4*)&Xs[(ty + 16 * i) * KV_PAD + k];
            #pragma unroll
            for (int j = 0; j < 4; j++) wv[j] = *(const float4*)&Wp[(tx + 16 * j) * KV_PAD + k];
            #pragma unroll
            for (int i = 0; i < 4; i++)
                #pragma unroll
                for (int j = 0; j < 4; j++) {
                    acc[i][j] += xv[i].x * wv[j].x;
                    acc[i][j] += xv[i].y * wv[j].y;
                    acc[i][j] += xv[i].z * wv[j].z;
                    acc[i][j] += xv[i].w * wv[j].w;
                }
        }

        #pragma unroll
        for (int i = 0; i < 4; i++) {
            int gn = base + ty + 16 * i;
            if (gn < Nk) {
                #pragma unroll
                for (int j = 0; j < 4; j++)
                    g_kvproj[gn * D + tx + 16 * j] = acc[i][j] + bd[j];
            }
        }
    }
}

// ---------------- kernel 4: zero output + denominators ----------------
__global__ void zero_kernel(float4* __restrict__ out4, int n4, int Nq) {
    int i = blockIdx.x * blockDim.x + threadIdx.x;
    int stride = gridDim.x * blockDim.x;
    for (int j = i; j < n4; j += stride) out4[j] = make_float4(0.f, 0.f, 0.f, 0.f);
    for (int j = i; j < Nq; j += stride) g_esum[j] = 0.f;
}

// ---------------- kernel 5: fused edge pass, 4 edges per thread for MLP ----------------
// Each thread = one float4 slot (sub) of 4 edges spaced Eq apart.
// All loads for the 4 edges are issued as independent batches -> MLP_eff ~4
// on the index loads, scalar loads, and the 256B kvproj gathers.
__global__ void edge_kernel(float4* __restrict__ out4, const int* __restrict__ ei32,
                            int E, int Eq, int Nq, int Nk) {
    int gt = blockIdx.x * blockDim.x + threadIdx.x;
    int e0 = gt >> 4;            // base edge in [0, Eq)
    if (e0 >= Eq) return;
    int sub = gt & 15;
    int is64 = g_is64;
    const long long* ei64 = (const long long*)ei32;

    int qi[4], ki[4];
    bool valid[4];
    #pragma unroll
    for (int j = 0; j < 4; j++) {
        int e = e0 + j * Eq;
        valid[j] = (e < E);
        int ee = valid[j] ? e : 0;
        int a, c;
        if (is64) { a = (int)ei64[ee]; c = (int)ei64[E + ee]; }
        else      { a = ei32[ee];      c = ei32[E + ee]; }
        qi[j] = min(max(a, 0), Nq - 1);
        ki[j] = min(max(c, 0), Nk - 1);
    }

    float w[4];
    #pragma unroll
    for (int j = 0; j < 4; j++) {
        float s = g_qs[qi[j]] + g_ks[ki[j]];
        s = s > 0.f ? s : ALPHA * s;
        w[j] = __expf(s);
    }

    if (sub == 0) {
        #pragma unroll
        for (int j = 0; j < 4; j++)
            if (valid[j]) atomicAdd(&g_esum[qi[j]], w[j]);
    }

    float4 v[4];
    #pragma unroll
    for (int j = 0; j < 4; j++)
        v[j] = ((const float4*)g_kvproj)[ki[j] * 16 + sub];

    #pragma unroll
    for (int j = 0; j < 4; j++) {
        if (valid[j]) {
            float4 r = make_float4(v[j].x * w[j], v[j].y * w[j],
                                   v[j].z * w[j], v[j].w * w[j]);
            atomicAdd(&out4[qi[j] * 16 + sub], r);
        }
    }
}

// ---------------- kernel 6: final normalization ----------------
__global__ void norm_kernel(float4* __restrict__ out4, int Nq) {
    int i = blockIdx.x * blockDim.x + threadIdx.x;
    if (i >= Nq * 16) return;
    float inv = 1.f / (g_esum[i >> 4] + EPS);
    float4 v = out4[i];
    out4[i] = make_float4(v.x * inv, v.y * inv, v.z * inv, v.w * inv);
}

// ---------------- launch ----------------
extern "C" void kernel_launch(void* const* d_in, const int* in_sizes, int n_in,
                              void* d_out, int out_size) {
    const float* q    = (const float*)d_in[0];
    const float* kv   = (const float*)d_in[1];
    const int*   ei32 = (const int*)d_in[2];
    const float* W    = (const float*)d_in[3];
    const float* b    = (const float*)d_in[4];
    const float* aw   = (const float*)d_in[5];
    const float* ab   = (const float*)d_in[6];
    int Nq = in_sizes[0] / D;
    int Nk = in_sizes[1] / D;
    int E  = in_sizes[2] / 2;
    float* out = (float*)d_out;

    sniff_kernel<<<1, 32>>>(ei32);
    prep_kernel<<<1, 128>>>(W, b, aw, ab);

    int Nmax = Nq > Nk ? Nq : Nk;
    int sc_blocks = (Nmax * 32 + 255) / 256;
    if (sc_blocks > 16384) sc_blocks = 16384;
    scalars_kernel<<<sc_blocks, 256>>>(q, kv, Nq, Nk);

    kvproj_kernel<<<592, 256>>>(kv, W, b, Nk);

    zero_kernel<<<2048, 256>>>((float4*)out, out_size / 4, Nq);

    int Eq = (E + 3) / 4;
    long long lanes = (long long)Eq * 16;
    int e_blocks = (int)((lanes + 255) / 256);
    edge_kernel<<<e_blocks, 256>>>((float4*)out, ei32, E, Eq, Nq, Nk);

    norm_kernel<<<(Nq * 16 + 255) / 256, 256>>>((float4*)out, Nq);
}

// round 17
// speedup vs baseline: 1.4448x; 1.0460x over previous
#include <cuda_runtime.h>
#include <cuda_bf16.h>
#include <cuda_fp16.h>

#define D 64
#define MAXN 100000
#define MAXE 1600000
#define ALPHA 0.2f
#define EPS 1e-10f

// ---------------- device scratch ----------------
__device__ __align__(16) float g_vq[D];
__device__ __align__(16) float g_vk[D];
__device__ float g_cq;
__device__ float g_ck;
__device__ int   g_is64;
__device__ __align__(16) float  g_qs[MAXN];
__device__ __align__(16) float  g_ks[MAXN];
__device__ __align__(16) __half g_kvh[MAXN * D];   // fp16 kv_proj table (12.8MB, L2-resident)
__device__ __align__(16) float  g_esum[MAXN];

// ---------------- kernel 0: sniff edge_index dtype ----------------
__global__ void sniff_kernel(const int* __restrict__ ei32) {
    if (threadIdx.x == 0) {
        int zeros = 0;
        for (int i = 1; i < 256; i += 2) zeros += (ei32[i] == 0);
        g_is64 = (zeros >= 120) ? 1 : 0;
    }
}

// ---------------- kernel 1: fold attend_w through proj_w ----------------
__global__ void prep_kernel(const float* __restrict__ W, const float* __restrict__ b,
                            const float* __restrict__ aw, const float* __restrict__ ab) {
    int t = threadIdx.x;
    if (t < D) {
        float s = 0.f;
        for (int d = 0; d < D; d++) s += aw[d] * W[d * D + t];
        g_vq[t] = s;
    } else {
        int k = t - D;
        float s = 0.f;
        for (int d = 0; d < D; d++) s += aw[D + d] * W[d * D + k];
        g_vk[k] = s;
    }
    if (t == 0) {
        float cq = 0.f, ck = 0.f;
        for (int d = 0; d < D; d++) { cq += b[d] * aw[d]; ck += b[d] * aw[D + d]; }
        g_cq = cq;
        g_ck = ck + ab[0];
    }
}

// ---------------- kernel 2: per-node attention scalars ----------------
__global__ void scalars_kernel(const float* __restrict__ q, const float* __restrict__ kv,
                               int Nq, int Nk) {
    int lane = threadIdx.x & 31;
    int warp = (blockIdx.x * blockDim.x + threadIdx.x) >> 5;
    int nwarps = (gridDim.x * blockDim.x) >> 5;
    float vq0 = g_vq[lane], vq1 = g_vq[lane + 32];
    float vk0 = g_vk[lane], vk1 = g_vk[lane + 32];
    float cq = g_cq, ck = g_ck;
    int Nmax = Nq > Nk ? Nq : Nk;
    for (int n = warp; n < Nmax; n += nwarps) {
        if (n < Nq) {
            float a = q[n * D + lane] * vq0 + q[n * D + lane + 32] * vq1;
            #pragma unroll
            for (int off = 16; off; off >>= 1) a += __shfl_xor_sync(0xffffffffu, a, off);
            if (lane == 0) g_qs[n] = a + cq;
        }
        if (n < Nk) {
            float a = kv[n * D + lane] * vk0 + kv[n * D + lane + 32] * vk1;
            #pragma unroll
            for (int off = 16; off; off >>= 1) a += __shfl_xor_sync(0xffffffffu, a, off);
            if (lane == 0) g_ks[n] = a + ck;
        }
    }
}

// ---------------- kernel 3: kv projection — register-blocked GEMM, fp16 output ----------------
#define KV_PAD 76
__global__ void kvproj_kernel(const float* __restrict__ kv, const float* __restrict__ W,
                              const float* __restrict__ b, int Nk) {
    __shared__ __align__(16) float Wp[D * KV_PAD];
    __shared__ __align__(16) float Xs[D * KV_PAD];
    int tid = threadIdx.x;
    int tx = tid & 15, ty = tid >> 4;

    for (int i = tid; i < D * 16; i += 256) {
        int d = i >> 4, kq = i & 15;
        float4 w4 = ((const float4*)W)[i];
        *(float4*)&Wp[d * KV_PAD + kq * 4] = w4;
    }
    float bd[4];
    #pragma unroll
    for (int j = 0; j < 4; j++) bd[j] = b[tx + 16 * j];

    int ntiles = (Nk + 63) >> 6;
    for (int tile = blockIdx.x; tile < ntiles; tile += gridDim.x) {
        int base = tile << 6;
        __syncthreads();
        for (int i = tid; i < D * 16; i += 256) {
            int n = i >> 4, kq = i & 15;
            int gn = base + n;
            float4 v = (gn < Nk) ? ((const float4*)kv)[gn * 16 + kq]
                                 : make_float4(0.f, 0.f, 0.f, 0.f);
            *(float4*)&Xs[n * KV_PAD + kq * 4] = v;
        }
        __syncthreads();

        float acc[4][4];
        #pragma unroll
        for (int i = 0; i < 4; i++)
            #pragma unroll
            for (int j = 0; j < 4; j++) acc[i][j] = 0.f;

        #pragma unroll
        for (int k = 0; k < D; k += 4) {
            float4 xv[4], wv[4];
            #pragma unroll
            for (int i = 0; i < 4; i++) xv[i] = *(const float4*)&Xs[(ty + 16 * i) * KV_PAD + k];
            #pragma unroll
            for (int j = 0; j < 4; j++) wv[j] = *(const float4*)&Wp[(tx + 16 * j) * KV_PAD + k];
            #pragma unroll
            for (int i = 0; i < 4; i++)
                #pragma unroll
                for (int j = 0; j < 4; j++) {
                    acc[i][j] += xv[i].x * wv[j].x;
                    acc[i][j] += xv[i].y * wv[j].y;
                    acc[i][j] += xv[i].z * wv[j].z;
                    acc[i][j] += xv[i].w * wv[j].w;
                }
        }

        #pragma unroll
        for (int i = 0; i < 4; i++) {
            int gn = base + ty + 16 * i;
            if (gn < Nk) {
                #pragma unroll
                for (int j = 0; j < 4; j++)
                    g_kvh[gn * D + tx + 16 * j] = __float2half_rn(acc[i][j] + bd[j]);
            }
        }
    }
}

// ---------------- kernel 4: zero output + denominators ----------------
__global__ void zero_kernel(float4* __restrict__ out4, int n4, int Nq) {
    int i = blockIdx.x * blockDim.x + threadIdx.x;
    int stride = gridDim.x * blockDim.x;
    for (int j = i; j < n4; j += stride) out4[j] = make_float4(0.f, 0.f, 0.f, 0.f);
    for (int j = i; j < Nq; j += stride) g_esum[j] = 0.f;
}

// ---------------- kernel 5: fused edge pass, 4 edges/thread, fp16 gather ----------------
// 16 lanes per edge; lane sub loads 4 halves (8B) -> gather 128B/edge.
// fp32 accumulation + fp32 RED to out preserves output precision (~1e-4 rel).
__global__ void edge_kernel(float4* __restrict__ out4, const int* __restrict__ ei32,
                            int E, int Eq, int Nq, int Nk) {
    int gt = blockIdx.x * blockDim.x + threadIdx.x;
    int e0 = gt >> 4;
    if (e0 >= Eq) return;
    int sub = gt & 15;
    int is64 = g_is64;
    const long long* ei64 = (const long long*)ei32;

    int qi[4], ki[4];
    bool valid[4];
    #pragma unroll
    for (int j = 0; j < 4; j++) {
        int e = e0 + j * Eq;
        valid[j] = (e < E);
        int ee = valid[j] ? e : 0;
        int a, c;
        if (is64) { a = (int)ei64[ee]; c = (int)ei64[E + ee]; }
        else      { a = ei32[ee];      c = ei32[E + ee]; }
        qi[j] = min(max(a, 0), Nq - 1);
        ki[j] = min(max(c, 0), Nk - 1);
    }

    float w[4];
    #pragma unroll
    for (int j = 0; j < 4; j++) {
        float s = g_qs[qi[j]] + g_ks[ki[j]];
        s = s > 0.f ? s : ALPHA * s;
        w[j] = __expf(s);
    }

    if (sub == 0) {
        #pragma unroll
        for (int j = 0; j < 4; j++)
            if (valid[j]) atomicAdd(&g_esum[qi[j]], w[j]);
    }

    uint2 u[4];
    const uint2* kvh2 = (const uint2*)g_kvh;   // 8B = 4 halves per lane
    #pragma unroll
    for (int j = 0; j < 4; j++)
        u[j] = kvh2[ki[j] * 16 + sub];

    #pragma unroll
    for (int j = 0; j < 4; j++) {
        if (valid[j]) {
            __half2 h0 = *reinterpret_cast<__half2*>(&u[j].x);
            __half2 h1 = *reinterpret_cast<__half2*>(&u[j].y);
            float2 f0 = __half22float2(h0);
            float2 f1 = __half22float2(h1);
            float4 r = make_float4(f0.x * w[j], f0.y * w[j],
                                   f1.x * w[j], f1.y * w[j]);
            atomicAdd(&out4[qi[j] * 16 + sub], r);
        }
    }
}

// ---------------- kernel 6: final normalization ----------------
__global__ void norm_kernel(float4* __restrict__ out4, int Nq) {
    int i = blockIdx.x * blockDim.x + threadIdx.x;
    if (i >= Nq * 16) return;
    float inv = 1.f / (g_esum[i >> 4] + EPS);
    float4 v = out4[i];
    out4[i] = make_float4(v.x * inv, v.y * inv, v.z * inv, v.w * inv);
}

// ---------------- launch ----------------
extern "C" void kernel_launch(void* const* d_in, const int* in_sizes, int n_in,
                              void* d_out, int out_size) {
    const float* q    = (const float*)d_in[0];
    const float* kv   = (const float*)d_in[1];
    const int*   ei32 = (const int*)d_in[2];
    const float* W    = (const float*)d_in[3];
    const float* b    = (const float*)d_in[4];
    const float* aw   = (const float*)d_in[5];
    const float* ab   = (const float*)d_in[6];
    int Nq = in_sizes[0] / D;
    int Nk = in_sizes[1] / D;
    int E  = in_sizes[2] / 2;
    float* out = (float*)d_out;

    sniff_kernel<<<1, 32>>>(ei32);
    prep_kernel<<<1, 128>>>(W, b, aw, ab);

    int Nmax = Nq > Nk ? Nq : Nk;
    int sc_blocks = (Nmax * 32 + 255) / 256;
    if (sc_blocks > 16384) sc_blocks = 16384;
    scalars_kernel<<<sc_blocks, 256>>>(q, kv, Nq, Nk);

    kvproj_kernel<<<592, 256>>>(kv, W, b, Nk);

    zero_kernel<<<2048, 256>>>((float4*)out, out_size / 4, Nq);

    int Eq = (E + 3) / 4;
    long long lanes = (long long)Eq * 16;
    int e_blocks = (int)((lanes + 255) / 256);
    edge_kernel<<<e_blocks, 256>>>((float4*)out, ei32, E, Eq, Nq, Nk);

    norm_kernel<<<(Nq * 16 + 255) / 256, 256>>>((float4*)out, Nq);
}